// round 3
// baseline (speedup 1.0000x reference)
#include <cuda_runtime.h>

// FOG: stride-2 occupancy downsample of 4M sparse voxels.
// Bitmap over the 2^29 key space replaces sort/unique:
//   rank(key) = popcount of set bits below key (== index in sorted unique list)
// v3: ownership counters at mark time -> the prefix scan touches only 8.4 MB
// of per-group counters instead of streaming the 64 MB bitmap; compacted
// coords are written by the owner threads in pass B.

#define HALF 512
#define NWORDS  (1u << 23)   // 2^29 keys / 64 bits per word (64 MB)
#define NGROUPS (1u << 21)   // 4-word groups (256 keys each)
#define MAXN 4000000

#define SCT 512                          // scan threads
#define SC_PER_T 4                       // counters per thread
#define SC_TILE (SCT * SC_PER_T)         // 2048 counters per tile
#define NT2 (NGROUPS / SC_TILE)          // 1024 tiles

// One fused clearable state region: [bits | counters | status | ticket]
#define STATE_U64 (NWORDS + NGROUPS / 2 + (NT2 + 1) / 2 + 1)
__device__ unsigned long long g_state[STATE_U64];
__device__ unsigned int g_prefix4[NGROUPS];   // rank at each 4-word group (8.4 MB)
__device__ unsigned int g_packed[MAXN];       // per-point (key<<3)|off (16 MB)
__device__ unsigned char g_flag[MAXN];        // per-point ownership (4 MB)
__device__ unsigned int g_total;

__device__ __forceinline__ unsigned long long* bitsPtr() { return g_state; }
__device__ __forceinline__ unsigned* cntPtr()    { return (unsigned*)(g_state + NWORDS); }
__device__ __forceinline__ unsigned* statusPtr() { return (unsigned*)(g_state + NWORDS + NGROUPS / 2); }
__device__ __forceinline__ unsigned* ticketPtr() { return (unsigned*)(g_state + NWORDS + NGROUPS / 2 + (NT2 + 1) / 2); }

// ---- pass A: key/off per point, mark bitmap, count new bits per group -----
__global__ void kA(const int4* __restrict__ coords, int n) {
    int i = blockIdx.x * blockDim.x + threadIdx.x;
    if (i >= n) return;
    int4 c = __ldcs(&coords[i]);  // {b, x, y, z}
    unsigned off = (unsigned)((c.y & 1) | ((c.z & 1) << 1) | ((c.w & 1) << 2));
    unsigned key = (((unsigned)c.x * HALF + (unsigned)(c.w >> 1)) * HALF
                    + (unsigned)(c.z >> 1)) * HALF + (unsigned)(c.y >> 1);
    g_packed[i] = (key << 3) | off;
    unsigned long long bit = 1ull << (key & 63);
    unsigned long long old = atomicOr(&bitsPtr()[key >> 6], bit);
    bool owner = (old & bit) == 0ull;
    g_flag[i] = owner ? 1 : 0;
    if (owner) atomicAdd(&cntPtr()[key >> 8], 1u);
}

// ---- fused counter scan: decoupled lookback over 2.1M group counts --------
__global__ void __launch_bounds__(SCT) kScan() {
    __shared__ unsigned s_tile;
    __shared__ unsigned s_warpsum[SCT / 32];
    __shared__ unsigned s_excl;

    if (threadIdx.x == 0) s_tile = atomicAdd(ticketPtr(), 1u);
    __syncthreads();
    const unsigned tile = s_tile;
    const unsigned base = tile * SC_TILE + threadIdx.x * SC_PER_T;

    uint4 cv = *reinterpret_cast<const uint4*>(&cntPtr()[base]);
    unsigned s = cv.x + cv.y + cv.z + cv.w;

    // block-wide scan of per-thread sums
    const unsigned lane = threadIdx.x & 31u, wid = threadIdx.x >> 5;
    unsigned inc = s;
#pragma unroll
    for (int d = 1; d < 32; d <<= 1) {
        unsigned x = __shfl_up_sync(0xffffffffu, inc, d);
        if (lane >= (unsigned)d) inc += x;
    }
    if (lane == 31) s_warpsum[wid] = inc;
    __syncthreads();
    if (threadIdx.x < SCT / 32) {
        unsigned v = s_warpsum[threadIdx.x];
#pragma unroll
        for (int d = 1; d < SCT / 32; d <<= 1) {
            unsigned x = __shfl_up_sync(0xffffu, v, d);
            if (threadIdx.x >= (unsigned)d) v += x;
        }
        s_warpsum[threadIdx.x] = v;
    }
    __syncthreads();
    const unsigned threadExcl = (wid ? s_warpsum[wid - 1] : 0u) + (inc - s);
    const unsigned tileAgg = s_warpsum[SCT / 32 - 1];

    unsigned* status = statusPtr();
    if (threadIdx.x == 0) {
        if (tile == 0) {
            atomicExch(&status[0], (tileAgg << 2) | 2u);
            s_excl = 0u;
        } else {
            atomicExch(&status[tile], (tileAgg << 2) | 1u);
        }
    }

    if (wid == 0 && tile > 0) {
        unsigned excl = 0;
        int look = (int)tile - 1;
        for (;;) {
            int idx = look - (int)lane;
            unsigned stv;
            do {
                stv = (idx >= 0) ? *(volatile unsigned*)&status[idx] : 2u;
            } while (__any_sync(0xffffffffu, (stv & 3u) == 0u));
            unsigned incMask = __ballot_sync(0xffffffffu, (stv & 3u) == 2u);
            if (incMask) {
                int firstInc = __ffs(incMask) - 1;
                unsigned contrib = (lane <= (unsigned)firstInc && idx >= 0) ? (stv >> 2) : 0u;
#pragma unroll
                for (int d = 16; d; d >>= 1) contrib += __shfl_down_sync(0xffffffffu, contrib, d);
                excl += __shfl_sync(0xffffffffu, contrib, 0);
                break;
            } else {
                unsigned contrib = (idx >= 0) ? (stv >> 2) : 0u;
#pragma unroll
                for (int d = 16; d; d >>= 1) contrib += __shfl_down_sync(0xffffffffu, contrib, d);
                excl += __shfl_sync(0xffffffffu, contrib, 0);
                look -= 32;
            }
        }
        if (lane == 0) {
            atomicExch(&status[tile], ((excl + tileAgg) << 2) | 2u);
            s_excl = excl;
            if (tile == NT2 - 1) g_total = excl + tileAgg;
        }
    }
    __syncthreads();

    unsigned rank = s_excl + threadExcl;
    uint4 pv;
    pv.x = rank;
    pv.y = rank + cv.x;
    pv.z = pv.y + cv.y;
    pv.w = pv.z + cv.z;
    *reinterpret_cast<uint4*>(&g_prefix4[base]) = pv;
}

// ---- pass B: rank gather, feats scatter-add, owner coords write, pad ------
__global__ void kB(const float* __restrict__ kw, float* __restrict__ feats,
                   float4* __restrict__ cout, int n) {
    int i = blockIdx.x * blockDim.x + threadIdx.x;
    if (i >= n) return;
    unsigned p = g_packed[i];
    unsigned key = p >> 3;
    unsigned off = p & 7u;
    unsigned w = key >> 6;
    unsigned b = key & 63u;
    unsigned g4 = w >> 2;
    const ulonglong2* gp = reinterpret_cast<const ulonglong2*>(&bitsPtr()[(size_t)g4 << 2]);
    ulonglong2 lo = __ldg(gp);
    ulonglong2 hi = __ldg(gp + 1);
    unsigned wi = w & 3u;
    unsigned r = __ldg(&g_prefix4[g4]);
    if (wi > 0) r += (unsigned)__popcll(lo.x);
    if (wi > 1) r += (unsigned)__popcll(lo.y);
    if (wi > 2) r += (unsigned)__popcll(hi.x);
    unsigned long long wsel = (wi == 0) ? lo.x : (wi == 1) ? lo.y : (wi == 2) ? hi.x : hi.y;
    r += (unsigned)__popcll(wsel & ((1ull << b) - 1ull));
    float contrib = (float)(1u << off) * __ldg(&kw[off]);
    atomicAdd(&feats[r], contrib);
    if (g_flag[i]) {
        float4 v = make_float4((float)(key >> 27),
                               (float)(key & 511u),
                               (float)((key >> 9) & 511u),
                               (float)((key >> 18) & 511u));
        cout[r] = v;
    }
    if ((unsigned)i >= g_total)
        __stcs(&cout[i], make_float4(-1.f, -1.f, -1.f, -1.f));
}

extern "C" void kernel_launch(void* const* d_in, const int* in_sizes, int n_in,
                              void* d_out, int out_size) {
    const int4*  coords = (const int4*)d_in[0];
    const float* kw     = (const float*)d_in[1];
    float* out = (float*)d_out;
    int n = in_sizes[0] / 4;                 // number of points
    float* feats = out + (size_t)4 * n;      // layout: coords (N,4) then feats (N,1)

    cudaMemsetAsync(feats, 0, (size_t)n * sizeof(float), 0);

    const int TB = 256;
    int nb = (n + TB - 1) / TB;
    kA<<<nb, TB>>>(coords, n);
    kScan<<<NT2, SCT>>>();
    kB<<<nb, TB>>>(kw, feats, (float4*)out, n);

    // clear bitmap + counters + lookback state for the next graph replay
    void* statePtr = nullptr;
    cudaGetSymbolAddress(&statePtr, g_state);
    cudaMemsetAsync(statePtr, 0, (size_t)STATE_U64 * sizeof(unsigned long long), 0);
}

// round 5
// speedup vs baseline: 1.7535x; 1.7535x over previous
#include <cuda_runtime.h>

// FOG: stride-2 occupancy downsample of 4M sparse voxels.
// Bitmap over the 2^29 key space replaces sort/unique:
//   rank(key) = popcount of set bits below key (== index in sorted unique list)
// v4 = v2 structure (best so far) + ILP in kA/kB + memset-based state clear.
// NOTE: kA's atomicOr result must stay UNUSED so it compiles to REDG.

#define HALF 512
#define NWORDS (1u << 23)             // 2^29 keys / 64 bits per word (64 MB)
#define TILE_T 512
#define TILE_I 8
#define TILE_WORDS (TILE_T * TILE_I)  // 4096 words per tile
#define NTILES (NWORDS / TILE_WORDS)  // 2048
#define MAXN 4000000

// One fused clearable state region: [bits | status | ticket]
#define STATE_U64 (NWORDS + (NTILES + 1) / 2 + 1)
__device__ unsigned long long g_state[STATE_U64];
__device__ unsigned int g_prefix4[NWORDS / 4];  // 8.4 MB: rank at each 4-word group
__device__ unsigned int g_packed[MAXN];         // 16 MB per-point (key<<3)|off
__device__ unsigned int g_total;

__device__ __forceinline__ unsigned long long* bitsPtr() { return g_state; }
__device__ __forceinline__ unsigned* statusPtr() { return (unsigned*)(g_state + NWORDS); }
__device__ __forceinline__ unsigned* ticketPtr() { return (unsigned*)(g_state + NWORDS + (NTILES + 1) / 2); }

// ---- pass A: key/off per point, mark bitmap (REDG atomics, 4 pts/thread) --
#define KA_P 4
__global__ void kA(const int4* __restrict__ coords, int n) {
    int base = (blockIdx.x * blockDim.x + threadIdx.x) * KA_P;
    if (base >= n) return;
    int4 c[KA_P];
    int m = n - base; if (m > KA_P) m = KA_P;
#pragma unroll
    for (int j = 0; j < KA_P; j++)
        if (j < m) c[j] = __ldcs(&coords[base + j]);
    unsigned key[KA_P], off[KA_P];
#pragma unroll
    for (int j = 0; j < KA_P; j++) {
        off[j] = (unsigned)((c[j].y & 1) | ((c[j].z & 1) << 1) | ((c[j].w & 1) << 2));
        key[j] = (((unsigned)c[j].x * HALF + (unsigned)(c[j].w >> 1)) * HALF
                  + (unsigned)(c[j].z >> 1)) * HALF + (unsigned)(c[j].y >> 1);
    }
#pragma unroll
    for (int j = 0; j < KA_P; j++)
        if (j < m) g_packed[base + j] = (key[j] << 3) | off[j];
#pragma unroll
    for (int j = 0; j < KA_P; j++)
        if (j < m) atomicOr(&bitsPtr()[key[j] >> 6], 1ull << (key[j] & 63));  // REDG
}

// ---- fused scan + compact: decoupled lookback -----------------------------
__global__ void __launch_bounds__(TILE_T) kScan(float4* __restrict__ cout) {
    __shared__ unsigned s_tile;
    __shared__ unsigned s_warpsum[TILE_T / 32];
    __shared__ unsigned s_excl;

    if (threadIdx.x == 0) s_tile = atomicAdd(ticketPtr(), 1u);
    __syncthreads();
    const unsigned tile = s_tile;
    const unsigned base = tile * TILE_WORDS + threadIdx.x * TILE_I;

    unsigned long long words[TILE_I];
    {
        const ulonglong2* p = reinterpret_cast<const ulonglong2*>(&bitsPtr()[base]);
#pragma unroll
        for (int j = 0; j < TILE_I / 2; j++) {
            ulonglong2 v = p[j];
            words[2 * j] = v.x; words[2 * j + 1] = v.y;
        }
    }
    unsigned pc[TILE_I], s = 0;
#pragma unroll
    for (int j = 0; j < TILE_I; j++) { pc[j] = (unsigned)__popcll(words[j]); s += pc[j]; }

    // block-wide exclusive scan of per-thread sums
    const unsigned lane = threadIdx.x & 31u, wid = threadIdx.x >> 5;
    unsigned inc = s;
#pragma unroll
    for (int d = 1; d < 32; d <<= 1) {
        unsigned x = __shfl_up_sync(0xffffffffu, inc, d);
        if (lane >= (unsigned)d) inc += x;
    }
    if (lane == 31) s_warpsum[wid] = inc;
    __syncthreads();
    if (threadIdx.x < TILE_T / 32) {
        unsigned v = s_warpsum[threadIdx.x];
#pragma unroll
        for (int d = 1; d < TILE_T / 32; d <<= 1) {
            unsigned x = __shfl_up_sync((1u << (TILE_T / 32)) - 1u, v, d);
            if (threadIdx.x >= (unsigned)d) v += x;
        }
        s_warpsum[threadIdx.x] = v;
    }
    __syncthreads();
    const unsigned wordExcl = (wid ? s_warpsum[wid - 1] : 0u) + (inc - s);
    const unsigned tileAgg  = s_warpsum[TILE_T / 32 - 1];

    unsigned* status = statusPtr();
    if (threadIdx.x == 0) {
        if (tile == 0) {
            atomicExch(&status[0], (tileAgg << 2) | 2u);
            s_excl = 0u;
            if (NTILES == 1) g_total = tileAgg;
        } else {
            atomicExch(&status[tile], (tileAgg << 2) | 1u);
        }
    }

    // warp 0: decoupled lookback
    if (wid == 0 && tile > 0) {
        unsigned excl = 0;
        int look = (int)tile - 1;
        for (;;) {
            int idx = look - (int)lane;
            unsigned stv;
            do {
                stv = (idx >= 0) ? *(volatile unsigned*)&status[idx] : 2u;
            } while (__any_sync(0xffffffffu, (stv & 3u) == 0u));
            unsigned incMask = __ballot_sync(0xffffffffu, (stv & 3u) == 2u);
            if (incMask) {
                int firstInc = __ffs(incMask) - 1;
                unsigned contrib = (lane <= (unsigned)firstInc && idx >= 0) ? (stv >> 2) : 0u;
#pragma unroll
                for (int d = 16; d; d >>= 1) contrib += __shfl_down_sync(0xffffffffu, contrib, d);
                excl += __shfl_sync(0xffffffffu, contrib, 0);
                break;
            } else {
                unsigned contrib = (idx >= 0) ? (stv >> 2) : 0u;
#pragma unroll
                for (int d = 16; d; d >>= 1) contrib += __shfl_down_sync(0xffffffffu, contrib, d);
                excl += __shfl_sync(0xffffffffu, contrib, 0);
                look -= 32;
            }
        }
        if (lane == 0) {
            atomicExch(&status[tile], ((excl + tileAgg) << 2) | 2u);
            s_excl = excl;
            if (tile == NTILES - 1) g_total = excl + tileAgg;
        }
    }
    __syncthreads();

    unsigned rank = s_excl + wordExcl;

    // per-4-word prefix (TILE_I==8 -> two entries per thread)
    {
        unsigned g4 = base >> 2;
        g_prefix4[g4]     = rank;
        g_prefix4[g4 + 1] = rank + pc[0] + pc[1] + pc[2] + pc[3];
    }

    // emit compacted sorted coords
    unsigned r = rank;
#pragma unroll
    for (int j = 0; j < TILE_I; j++) {
        unsigned long long word = words[j];
        unsigned keybase = (base + j) << 6;
        while (word) {
            unsigned b = (unsigned)__ffsll((long long)word) - 1u;
            word &= word - 1ull;
            unsigned key = keybase + b;
            float4 v = make_float4((float)(key >> 27),
                                   (float)(key & 511u),
                                   (float)((key >> 9) & 511u),
                                   (float)((key >> 18) & 511u));
            __stcs(&cout[r], v);
            r++;
        }
    }
}

// ---- pass B: rank gather + feats scatter-add + pad (2 pts/thread) ---------
#define KB_P 2
__global__ void kB(const float* __restrict__ kw, float* __restrict__ feats,
                   float4* __restrict__ cout, int n) {
    int base = (blockIdx.x * blockDim.x + threadIdx.x) * KB_P;
    if (base >= n) return;
    int m = n - base; if (m > KB_P) m = KB_P;
    unsigned p[KB_P];
#pragma unroll
    for (int j = 0; j < KB_P; j++)
        if (j < m) p[j] = g_packed[base + j];
    ulonglong2 lo[KB_P], hi[KB_P];
    unsigned pre[KB_P];
#pragma unroll
    for (int j = 0; j < KB_P; j++) {
        if (j >= m) continue;
        unsigned g4 = (p[j] >> 3) >> 8;  // key>>6>>2
        const ulonglong2* gp = reinterpret_cast<const ulonglong2*>(&bitsPtr()[(size_t)g4 << 2]);
        lo[j] = __ldg(gp);
        hi[j] = __ldg(gp + 1);
        pre[j] = __ldg(&g_prefix4[g4]);
    }
    unsigned total = g_total;
#pragma unroll
    for (int j = 0; j < KB_P; j++) {
        if (j >= m) continue;
        unsigned key = p[j] >> 3;
        unsigned off = p[j] & 7u;
        unsigned b = key & 63u;
        unsigned wi = (key >> 6) & 3u;
        unsigned r = pre[j];
        if (wi > 0) r += (unsigned)__popcll(lo[j].x);
        if (wi > 1) r += (unsigned)__popcll(lo[j].y);
        if (wi > 2) r += (unsigned)__popcll(hi[j].x);
        unsigned long long wsel = (wi == 0) ? lo[j].x : (wi == 1) ? lo[j].y
                                 : (wi == 2) ? hi[j].x : hi[j].y;
        r += (unsigned)__popcll(wsel & ((1ull << b) - 1ull));
        float contrib = (float)(1u << off) * __ldg(&kw[off]);
        atomicAdd(&feats[r], contrib);
        if ((unsigned)(base + j) >= total)
            __stcs(&cout[base + j], make_float4(-1.f, -1.f, -1.f, -1.f));
    }
}

extern "C" void kernel_launch(void* const* d_in, const int* in_sizes, int n_in,
                              void* d_out, int out_size) {
    const int4*  coords = (const int4*)d_in[0];
    const float* kw     = (const float*)d_in[1];
    float* out = (float*)d_out;
    int n = in_sizes[0] / 4;                 // number of points
    float* feats = out + (size_t)4 * n;      // layout: coords (N,4) then feats (N,1)

    cudaMemsetAsync(feats, 0, (size_t)n * sizeof(float), 0);

    const int TB = 256;
    kA<<<(n + TB * KA_P - 1) / (TB * KA_P), TB>>>(coords, n);
    kScan<<<NTILES, TILE_T>>>((float4*)out);
    kB<<<(n + TB * KB_P - 1) / (TB * KB_P), TB>>>(kw, feats, (float4*)out, n);

    // clear bitmap + lookback status + ticket for the next graph replay
    void* statePtr = nullptr;
    cudaGetSymbolAddress(&statePtr, g_state);
    cudaMemsetAsync(statePtr, 0, (size_t)STATE_U64 * sizeof(unsigned long long), 0);
}